// round 15
// baseline (speedup 1.0000x reference)
#include <cuda_runtime.h>
#include <cstdint>

// Problem constants (fixed shapes per reference)
#define NSPANS 4096
#define TMAX   16
#define HDIM   768
#define H4     192          // HDIM / 4 (float4 lanes per row)
#define R4     576          // 3 * H4 = float4 per span repr (half output row)
#define NPAIRS 16384
#define SL     2048         // S * L
#define NENT   (2 * NPAIRS) // 32768 (pair, side) entries
#define CAP    96           // bucket capacity per span (mean 8, sigma 2.9)

// Bucket scratch. Device globals are zero-initialized at load; scatter_kernel
// re-zeroes cursor after use, so every launch/replay sees it zeroed.
__device__ int g_cursor[NSPANS];
__device__ int g_bucket[NSPANS * CAP];   // packed entry: p*2 + side

// ---------------------------------------------------------------- fill
// One thread per (pair, side) entry: exactly one atomic + one store, 32K
// threads -> atomic latency fully overlapped. Slot order within a span is
// atomic-nondeterministic, but each entry encodes its own output slot, so
// the final output is deterministic.
__global__ __launch_bounds__(128) void fill_kernel(
    const int* __restrict__ pair_i,
    const int* __restrict__ pair_j)
{
    const int e    = blockIdx.x * 128 + threadIdx.x;   // 0..NENT-1
    const int p    = e >> 1;
    const int span = (e & 1) ? __ldg(pair_j + p) : __ldg(pair_i + p);
    const int pos  = atomicAdd(&g_cursor[span], 1);
    if (pos < CAP) g_bucket[span * CAP + pos] = e;
}

// ---------------------------------------------------------------- scatter
// One block of 192 threads per span; thread t owns lane t of ALL THREE
// repr segments in registers (vf=first, vm=clamped 16-wide mean, vl=last;
// 18 independent hidden loads -> high MLP, ~8 blocks resident per SM).
// For each (pair, side) occurrence the block writes the contiguous 9216-B
// half-row as 3 coalesced 3072-B segments, 2 entries unrolled per iteration.
__global__ __launch_bounds__(192) void scatter_kernel(
    const float* __restrict__ hidden,
    const int*   __restrict__ span_doc,
    const int*   __restrict__ span_tok,
    const int*   __restrict__ span_len,
    float4*      __restrict__ out)
{
    const int n = blockIdx.x;
    const int t = threadIdx.x;        // 0..191

    __shared__ int s_tok[TMAX];
    __shared__ int s_ent[CAP];

    const int cnt0 = g_cursor[n];               // uniform broadcast load
    const int cnt  = (cnt0 < CAP) ? cnt0 : CAP;

    if (t < TMAX) s_tok[t] = __ldg(span_tok + n * TMAX + t);
    if (t >= 64 && t - 64 < cnt) s_ent[t - 64] = g_bucket[n * CAP + (t - 64)];
    __syncthreads();

    const int doc   = __ldg(span_doc + n);
    const int len   = __ldg(span_len + n);   // 1..16
    const int lenm1 = len - 1;

    const float4* __restrict__ base =
        reinterpret_cast<const float4*>(hidden) + (size_t)doc * SL * H4;

    // first / last rows
    const float4 vf = __ldg(base + (size_t)s_tok[0] * H4 + t);
    const float4 vl = __ldg(base + (size_t)s_tok[lenm1] * H4 + t);

    // mean: 16 independent clamped loads
    float4 acc = make_float4(0.f, 0.f, 0.f, 0.f);
    #pragma unroll
    for (int k = 0; k < TMAX; ++k) {
        const int tt = (k < len) ? k : lenm1;  // clamp -> L1-hit duplicate
        const float w = (k < len) ? 1.0f : 0.0f;
        const float4 g = __ldg(base + (size_t)s_tok[tt] * H4 + t);
        acc.x += g.x * w; acc.y += g.y * w;
        acc.z += g.z * w; acc.w += g.w * w;
    }
    const float inv = 1.0f / (float)len;
    const float4 vm = make_float4(acc.x * inv, acc.y * inv,
                                  acc.z * inv, acc.w * inv);

    int k = 0;
    for (; k + 2 <= cnt; k += 2) {
        const int e0 = s_ent[k];
        const int e1 = s_ent[k + 1];
        float4* __restrict__ o0 = out + (size_t)e0 * R4;
        float4* __restrict__ o1 = out + (size_t)e1 * R4;
        __stcs(o0 + t,       vf);
        __stcs(o1 + t,       vf);
        __stcs(o0 + 192 + t, vm);
        __stcs(o1 + 192 + t, vm);
        __stcs(o0 + 384 + t, vl);
        __stcs(o1 + 384 + t, vl);
    }
    if (k < cnt) {
        const int e = s_ent[k];
        float4* __restrict__ o = out + (size_t)e * R4;
        __stcs(o + t,       vf);
        __stcs(o + 192 + t, vm);
        __stcs(o + 384 + t, vl);
    }

    // Reset cursor for the next graph replay (after all threads read cnt).
    __syncthreads();
    if (t == 0) g_cursor[n] = 0;
}

extern "C" void kernel_launch(void* const* d_in, const int* in_sizes, int n_in,
                              void* d_out, int out_size)
{
    const float* hidden   = (const float*)d_in[0];
    const int*   span_doc = (const int*)  d_in[1];
    const int*   span_tok = (const int*)  d_in[2];
    const int*   span_len = (const int*)  d_in[3];
    const int*   pair_i   = (const int*)  d_in[4];
    const int*   pair_j   = (const int*)  d_in[5];
    float4*      out      = (float4*)     d_out;

    fill_kernel<<<NENT / 128, 128>>>(pair_i, pair_j);
    scatter_kernel<<<NSPANS, 192>>>(hidden, span_doc, span_tok, span_len, out);
}

// round 16
// speedup vs baseline: 1.0121x; 1.0121x over previous
#include <cuda_runtime.h>
#include <cstdint>

// Problem constants (fixed shapes per reference)
#define NSPANS 4096
#define TMAX   16
#define HDIM   768
#define H4     192          // HDIM / 4 (float4 lanes per row)
#define R4     576          // 3 * H4 = float4 per span repr (half output row)
#define NPAIRS 16384
#define SL     2048         // S * L
#define CAP    96           // bucket capacity per span (mean 8, sigma 2.9)

// Bucket scratch. Device globals are zero-initialized at load; scatter_kernel
// re-zeroes cursor after use, so every launch/replay sees it zeroed.
__device__ int g_cursor[NSPANS];
__device__ int g_bucket[NSPANS * CAP];   // packed entry: p*2 + side

// ---------------------------------------------------------------- fill
// One thread per pair pushes both (pair, side) entries into the spans'
// buckets (R13 form — measured fastest). Slot order is atomic-
// nondeterministic, but each entry encodes its own output slot, so the
// final output is deterministic.
__global__ __launch_bounds__(128) void fill_kernel(
    const int* __restrict__ pair_i,
    const int* __restrict__ pair_j)
{
    const int p  = blockIdx.x * 128 + threadIdx.x;   // 0..NPAIRS-1
    const int si = __ldg(pair_i + p);
    const int sj = __ldg(pair_j + p);
    const int posi = atomicAdd(&g_cursor[si], 1);
    const int posj = atomicAdd(&g_cursor[sj], 1);
    if (posi < CAP) g_bucket[si * CAP + posi] = p * 2;
    if (posj < CAP) g_bucket[sj * CAP + posj] = p * 2 + 1;
}

// ---------------------------------------------------------------- scatter
// (R14 form — measured fastest.) One block of 192 threads per span; thread t
// owns lane t of ALL THREE repr segments in registers (vf=first, vm=clamped
// 16-wide mean, vl=last; 18 independent hidden loads -> high MLP, ~8 blocks
// resident per SM). For each (pair, side) occurrence the block writes the
// contiguous 9216-B half-row as 3 coalesced 3072-B evict-first segments.
__global__ __launch_bounds__(192) void scatter_kernel(
    const float* __restrict__ hidden,
    const int*   __restrict__ span_doc,
    const int*   __restrict__ span_tok,
    const int*   __restrict__ span_len,
    float4*      __restrict__ out)
{
    const int n = blockIdx.x;
    const int t = threadIdx.x;        // 0..191

    __shared__ int s_tok[TMAX];
    __shared__ int s_ent[CAP];

    const int cnt0 = g_cursor[n];               // uniform broadcast load
    const int cnt  = (cnt0 < CAP) ? cnt0 : CAP;

    if (t < TMAX) s_tok[t] = __ldg(span_tok + n * TMAX + t);
    if (t >= 64 && t - 64 < cnt) s_ent[t - 64] = g_bucket[n * CAP + (t - 64)];
    __syncthreads();

    const int doc   = __ldg(span_doc + n);
    const int len   = __ldg(span_len + n);   // 1..16
    const int lenm1 = len - 1;

    const float4* __restrict__ base =
        reinterpret_cast<const float4*>(hidden) + (size_t)doc * SL * H4;

    // first / last rows
    const float4 vf = __ldg(base + (size_t)s_tok[0] * H4 + t);
    const float4 vl = __ldg(base + (size_t)s_tok[lenm1] * H4 + t);

    // mean: 16 independent clamped loads
    float4 acc = make_float4(0.f, 0.f, 0.f, 0.f);
    #pragma unroll
    for (int k = 0; k < TMAX; ++k) {
        const int tt = (k < len) ? k : lenm1;  // clamp -> L1-hit duplicate
        const float w = (k < len) ? 1.0f : 0.0f;
        const float4 g = __ldg(base + (size_t)s_tok[tt] * H4 + t);
        acc.x += g.x * w; acc.y += g.y * w;
        acc.z += g.z * w; acc.w += g.w * w;
    }
    const float inv = 1.0f / (float)len;
    const float4 vm = make_float4(acc.x * inv, acc.y * inv,
                                  acc.z * inv, acc.w * inv);

    for (int k = 0; k < cnt; ++k) {
        const int e = s_ent[k];
        float4* __restrict__ o = out + (size_t)e * R4;
        __stcs(o + t,       vf);
        __stcs(o + 192 + t, vm);
        __stcs(o + 384 + t, vl);
    }

    // Reset cursor for the next graph replay (after all threads read cnt).
    __syncthreads();
    if (t == 0) g_cursor[n] = 0;
}

extern "C" void kernel_launch(void* const* d_in, const int* in_sizes, int n_in,
                              void* d_out, int out_size)
{
    const float* hidden   = (const float*)d_in[0];
    const int*   span_doc = (const int*)  d_in[1];
    const int*   span_tok = (const int*)  d_in[2];
    const int*   span_len = (const int*)  d_in[3];
    const int*   pair_i   = (const int*)  d_in[4];
    const int*   pair_j   = (const int*)  d_in[5];
    float4*      out      = (float4*)     d_out;

    fill_kernel<<<NPAIRS / 128, 128>>>(pair_i, pair_j);
    scatter_kernel<<<NSPANS, 192>>>(hidden, span_doc, span_tok, span_len, out);
}